// round 14
// baseline (speedup 1.0000x reference)
#include <cuda_runtime.h>
#include <cuda_bf16.h>
#include <cstdint>

#define N_ROWS   4194304
#define DIM      64
#define NUM_SEG  131072
#define NBLK     296          // 2 CTAs/SM x 148 SMs -- all resident in wave 1
#define NTHREADS 256
#define NTILES   (N_ROWS / 256)

// ---------------- scratch (no allocations allowed) ----------------
__device__ float    g_segsum[NUM_SEG];
__device__ unsigned g_count = 0;   // barrier arrival counter (returns to 0)
__device__ unsigned g_sense = 0;   // barrier sense (0 -> 1 -> 0 per call)

// Sense-reversing software grid barrier. All NBLK blocks are co-resident
// (enforced by __launch_bounds__(256,2) occupancy + grid size), so spinning
// is deadlock-free. State returns to {count=0, sense=0} after the two
// barriers in this kernel -> deterministic across graph replays.
__device__ __forceinline__ void grid_barrier(unsigned want) {
    __threadfence();          // release: make this thread's stores visible
    __syncthreads();
    if (threadIdx.x == 0) {
        unsigned old = atomicAdd(&g_count, 1);
        if (old == NBLK - 1) {
            g_count = 0;
            __threadfence();
            atomicExch(&g_sense, want);
        } else {
            while (*(volatile unsigned*)&g_sense != want) __nanosleep(32);
        }
        __threadfence();      // acquire: order subsequent loads
    }
    __syncthreads();
}

// ---------------- single persistent kernel: init + GEMV/exp/sum + norm -----
// Phase 1 body is byte-equivalent to the proven k_main (16 lanes/row, 512B
// contiguous per LDG.128, two 8-deep load batches, run-length-merged
// atomicAdds, __ldcs streaming of X); it just loops over tiles with stride
// NBLK instead of one tile per block.
__global__ void __launch_bounds__(NTHREADS, 2) k_fused(
    const float* __restrict__ X,
    const int*   __restrict__ seg,
    const float* __restrict__ W,
    const float* __restrict__ b,
    float*       __restrict__ out)
{
    const int tid  = threadIdx.x;
    const int lane = tid & 31;
    const int col  = lane & 15;
    const int half = lane >> 4;
    const int warpInBlk = tid >> 5;

    // ---- phase 0: zero g_segsum (grid-stride, float4) ----
    for (int i = blockIdx.x * NTHREADS + tid; i < NUM_SEG / 4; i += NBLK * NTHREADS)
        reinterpret_cast<float4*>(g_segsum)[i] = make_float4(0.f, 0.f, 0.f, 0.f);

    grid_barrier(1);

    // ---- phase 1: fused GEMV + exp + segment sum ----
    const float w0 = __ldg(&W[col * 4 + 0]);
    const float w1 = __ldg(&W[col * 4 + 1]);
    const float w2 = __ldg(&W[col * 4 + 2]);
    const float w3 = __ldg(&W[col * 4 + 3]);
    const float b0 = __ldg(&b[0]);

    const float4* __restrict__ Xv = reinterpret_cast<const float4*>(X);
    const bool isHead = (col == 0);

    for (int tile = blockIdx.x; tile < NTILES; tile += NBLK) {
        const int rowBase = tile * 256 + warpInBlk * 32;
        const int myRow0  = rowBase + 16 * half;
        const size_t base = (size_t)myRow0 * (DIM / 4) + col;

        // head lanes preload their 16 seg ids (aligned int4 x4)
        int sid[16];
        if (isHead) {
            const int4* s4 = reinterpret_cast<const int4*>(seg + myRow0);
#pragma unroll
            for (int q = 0; q < 4; ++q) {
                int4 v = __ldg(&s4[q]);
                sid[4 * q + 0] = v.x; sid[4 * q + 1] = v.y;
                sid[4 * q + 2] = v.z; sid[4 * q + 3] = v.w;
            }
        }

        int   curSeg = -1;
        float curAcc = 0.0f;

#pragma unroll
        for (int ii = 0; ii < 16; ii += 8) {
            float4 xs[8];
#pragma unroll
            for (int u = 0; u < 8; ++u)
                xs[u] = __ldcs(&Xv[base + (size_t)(ii + u) * (DIM / 4)]);

            float accs[8];
#pragma unroll
            for (int u = 0; u < 8; ++u) {
                float a = xs[u].x * w0 + xs[u].y * w1 + xs[u].z * w2 + xs[u].w * w3;
#pragma unroll
                for (int d = 8; d >= 1; d >>= 1)
                    a += __shfl_xor_sync(0xffffffffu, a, d);
                accs[u] = a;
            }

            if (isHead) {
                float e[8];
#pragma unroll
                for (int u = 0; u < 8; ++u)
                    e[u] = __expf(accs[u] + b0);

                float4* ov = reinterpret_cast<float4*>(out + myRow0 + ii);
                ov[0] = make_float4(e[0], e[1], e[2], e[3]);
                ov[1] = make_float4(e[4], e[5], e[6], e[7]);

#pragma unroll
                for (int u = 0; u < 8; ++u) {
                    int s = sid[ii + u];
                    if (s != curSeg) {
                        if (curSeg >= 0) atomicAdd(&g_segsum[curSeg], curAcc);
                        curSeg = s;
                        curAcc = e[u];
                    } else {
                        curAcc += e[u];
                    }
                }
            }
        }
        if (isHead && curSeg >= 0) atomicAdd(&g_segsum[curSeg], curAcc);
    }

    grid_barrier(0);   // sense returns to initial value -> replay-safe

    // ---- phase 2: normalize (8 rows / unit, grid-stride) ----
    for (int t = blockIdx.x * NTHREADS + tid; t < N_ROWS / 8; t += NBLK * NTHREADS) {
        const int4* sv = reinterpret_cast<const int4*>(seg) + 2 * t;
        float4*     ov = reinterpret_cast<float4*>(out) + 2 * t;

        int4   sa = __ldg(&sv[0]);
        int4   sb = __ldg(&sv[1]);
        float4 va = ov[0];
        float4 vb = ov[1];

        int   s[8] = { sa.x, sa.y, sa.z, sa.w, sb.x, sb.y, sb.z, sb.w };
        float v[8] = { va.x, va.y, va.z, va.w, vb.x, vb.y, vb.z, vb.w };

        int   cur = s[0];
        float inv = __frcp_rn(g_segsum[cur]);
#pragma unroll
        for (int u = 0; u < 8; ++u) {
            if (s[u] != cur) { cur = s[u]; inv = __frcp_rn(g_segsum[cur]); }
            v[u] *= inv;
        }

        ov[0] = make_float4(v[0], v[1], v[2], v[3]);
        ov[1] = make_float4(v[4], v[5], v[6], v[7]);
    }
}

// ---------------- launch ----------------
extern "C" void kernel_launch(void* const* d_in, const int* in_sizes, int n_in,
                              void* d_out, int out_size)
{
    const float* X   = (const float*)d_in[0];
    const int*   seg = (const int*)  d_in[1];
    const float* W   = (const float*)d_in[2];
    const float* b   = (const float*)d_in[3];
    float* out = (float*)d_out;

    k_fused<<<NBLK, NTHREADS>>>(X, seg, W, b, out);
}

// round 16
// speedup vs baseline: 1.0678x; 1.0678x over previous
#include <cuda_runtime.h>
#include <cuda_bf16.h>
#include <cstdint>

#define N_ROWS   4194304
#define DIM      64
#define NUM_SEG  131072
#define NBLK     444          // 3 CTAs/SM x 148 SMs -- all resident in wave 1
#define NTHREADS 256
#define NTILES   (N_ROWS / 256)

// ---------------- scratch (no allocations allowed) ----------------
__device__ float    g_segsum[NUM_SEG];
__device__ unsigned g_count = 0;   // barrier arrival counter (returns to 0)
__device__ unsigned g_sense = 0;   // barrier sense (0 -> 1 -> 0 per call)

// Sense-reversing software grid barrier. All NBLK blocks are co-resident
// (74 regs < 85-reg cap from __launch_bounds__(256,3); no smem), so spinning
// is deadlock-free. State returns to {count=0, sense=0} after the two
// barriers in this kernel -> deterministic across graph replays.
__device__ __forceinline__ void grid_barrier(unsigned want) {
    __threadfence();          // release: make this thread's stores visible
    __syncthreads();
    if (threadIdx.x == 0) {
        unsigned old = atomicAdd(&g_count, 1);
        if (old == NBLK - 1) {
            g_count = 0;
            __threadfence();
            atomicExch(&g_sense, want);
        } else {
            while (*(volatile unsigned*)&g_sense != want) __nanosleep(32);
        }
        __threadfence();      // acquire: order subsequent loads
    }
    __syncthreads();
}

// ---------------- single persistent kernel: init + GEMV/exp/sum + norm -----
// Phase 1 body is byte-equivalent to the proven k_main (16 lanes/row, 512B
// contiguous per LDG.128, two 8-deep load batches, run-length-merged
// atomicAdds, __ldcs streaming of X); loops over tiles with stride NBLK.
// R14 showed 2 CTAs/SM caps DRAM at 6.0 TB/s (occ 24%); 3 CTAs/SM restores
// the SM-level MLP of the multi-kernel version.
__global__ void __launch_bounds__(NTHREADS, 3) k_fused(
    const float* __restrict__ X,
    const int*   __restrict__ seg,
    const float* __restrict__ W,
    const float* __restrict__ b,
    float*       __restrict__ out)
{
    const int tid  = threadIdx.x;
    const int lane = tid & 31;
    const int col  = lane & 15;
    const int half = lane >> 4;
    const int warpInBlk = tid >> 5;

    // ---- phase 0: zero g_segsum (grid-stride, float4) ----
    for (int i = blockIdx.x * NTHREADS + tid; i < NUM_SEG / 4; i += NBLK * NTHREADS)
        reinterpret_cast<float4*>(g_segsum)[i] = make_float4(0.f, 0.f, 0.f, 0.f);

    grid_barrier(1);

    // ---- phase 1: fused GEMV + exp + segment sum ----
    const float w0 = __ldg(&W[col * 4 + 0]);
    const float w1 = __ldg(&W[col * 4 + 1]);
    const float w2 = __ldg(&W[col * 4 + 2]);
    const float w3 = __ldg(&W[col * 4 + 3]);
    const float b0 = __ldg(&b[0]);

    const float4* __restrict__ Xv = reinterpret_cast<const float4*>(X);
    const bool isHead = (col == 0);

    for (int tile = blockIdx.x; tile < NTILES; tile += NBLK) {
        const int rowBase = tile * 256 + warpInBlk * 32;
        const int myRow0  = rowBase + 16 * half;
        const size_t base = (size_t)myRow0 * (DIM / 4) + col;

        // head lanes preload their 16 seg ids (aligned int4 x4)
        int sid[16];
        if (isHead) {
            const int4* s4 = reinterpret_cast<const int4*>(seg + myRow0);
#pragma unroll
            for (int q = 0; q < 4; ++q) {
                int4 v = __ldg(&s4[q]);
                sid[4 * q + 0] = v.x; sid[4 * q + 1] = v.y;
                sid[4 * q + 2] = v.z; sid[4 * q + 3] = v.w;
            }
        }

        int   curSeg = -1;
        float curAcc = 0.0f;

#pragma unroll
        for (int ii = 0; ii < 16; ii += 8) {
            float4 xs[8];
#pragma unroll
            for (int u = 0; u < 8; ++u)
                xs[u] = __ldcs(&Xv[base + (size_t)(ii + u) * (DIM / 4)]);

            float accs[8];
#pragma unroll
            for (int u = 0; u < 8; ++u) {
                float a = xs[u].x * w0 + xs[u].y * w1 + xs[u].z * w2 + xs[u].w * w3;
#pragma unroll
                for (int d = 8; d >= 1; d >>= 1)
                    a += __shfl_xor_sync(0xffffffffu, a, d);
                accs[u] = a;
            }

            if (isHead) {
                float e[8];
#pragma unroll
                for (int u = 0; u < 8; ++u)
                    e[u] = __expf(accs[u] + b0);

                float4* ov = reinterpret_cast<float4*>(out + myRow0 + ii);
                ov[0] = make_float4(e[0], e[1], e[2], e[3]);
                ov[1] = make_float4(e[4], e[5], e[6], e[7]);

#pragma unroll
                for (int u = 0; u < 8; ++u) {
                    int s = sid[ii + u];
                    if (s != curSeg) {
                        if (curSeg >= 0) atomicAdd(&g_segsum[curSeg], curAcc);
                        curSeg = s;
                        curAcc = e[u];
                    } else {
                        curAcc += e[u];
                    }
                }
            }
        }
        if (isHead && curSeg >= 0) atomicAdd(&g_segsum[curSeg], curAcc);
    }

    grid_barrier(0);   // sense returns to initial value -> replay-safe

    // ---- phase 2: normalize (8 rows / unit, grid-stride) ----
    for (int t = blockIdx.x * NTHREADS + tid; t < N_ROWS / 8; t += NBLK * NTHREADS) {
        const int4* sv = reinterpret_cast<const int4*>(seg) + 2 * t;
        float4*     ov = reinterpret_cast<float4*>(out) + 2 * t;

        int4   sa = __ldg(&sv[0]);
        int4   sb = __ldg(&sv[1]);
        float4 va = ov[0];
        float4 vb = ov[1];

        int   s[8] = { sa.x, sa.y, sa.z, sa.w, sb.x, sb.y, sb.z, sb.w };
        float v[8] = { va.x, va.y, va.z, va.w, vb.x, vb.y, vb.z, vb.w };

        int   cur = s[0];
        float inv = __frcp_rn(g_segsum[cur]);
#pragma unroll
        for (int u = 0; u < 8; ++u) {
            if (s[u] != cur) { cur = s[u]; inv = __frcp_rn(g_segsum[cur]); }
            v[u] *= inv;
        }

        ov[0] = make_float4(v[0], v[1], v[2], v[3]);
        ov[1] = make_float4(v[4], v[5], v[6], v[7]);
    }
}

// ---------------- launch ----------------
extern "C" void kernel_launch(void* const* d_in, const int* in_sizes, int n_in,
                              void* d_out, int out_size)
{
    const float* X   = (const float*)d_in[0];
    const int*   seg = (const int*)  d_in[1];
    const float* W   = (const float*)d_in[2];
    const float* b   = (const float*)d_in[3];
    float* out = (float*)d_out;

    k_fused<<<NBLK, NTHREADS>>>(X, seg, W, b, out);
}